// round 8
// baseline (speedup 1.0000x reference)
#include <cuda_runtime.h>
#include <cuda_fp16.h>
#include <cstdint>

// NTXentLoss fused, FP8 mma.sync, persistent-balanced edition.
// B=8192, D=128, G=16, T=0.5
//   prep:     normalize, fold 2*log2e into zis, cast e4m3; exact fp32 diag.
//   main:     148 CTAs x 512 threads; 4096 units (64 rowtiles x 64 chunks of
//             128x128). Contiguous unit ranges per CTA (<=28 units). Per unit:
//             mma.sync.m16n8k32.e4m3, ex2.approx epilogue + block mask,
//             quad-reduced row partials -> g_unit (deterministic).
//   final1/2: per-row sum of 128 partials + loss; reduce 64 -> scalar.
// logits in log2 domain: acc = (sim/T)*log2e, exp = exp2(acc).

#define B_N 8192
#define D_K 128
#define NUNITS 4096                  // 64 rowtiles x 64 chunks
#define NCTAS 148
#define LOG2E 1.4426950408889634f
#define CHUNK_BYTES (128 * 128)      // 16 KB fp8 B chunk
#define SMEM_TOTAL (4 * CHUNK_BYTES) // 64 KB ring

__device__ uint32_t g_a8[B_N * 32];   // zis e4m3, scaled by (1/norm)*2*log2e
__device__ uint32_t g_b8[B_N * 32];   // zjs e4m3, scaled by (1/norm)
__device__ float g_diag[B_N];         // exact fp32 cosine(zis_i, zjs_i)
__device__ float g_unit[NUNITS * 256];// per-unit, per-half row partials (4 MB)
__device__ float g_partial[64];

__device__ __forceinline__ uint32_t smem_u32(const void* p) {
    return (uint32_t)__cvta_generic_to_shared(p);
}
__device__ __forceinline__ float ex2f(float x) {
    float r;
    asm("ex2.approx.ftz.f32 %0, %1;" : "=f"(r) : "f"(x));
    return r;
}

// ---------------------------------------------------------------------------
// prep: one warp per row; e4m3 conversion + exact diag, one pass.
// ---------------------------------------------------------------------------
__global__ void __launch_bounds__(256) prep_kernel(const float* __restrict__ zis,
                                                   const float* __restrict__ zjs) {
    int row = (blockIdx.x * 256 + threadIdx.x) >> 5;
    int lane = threadIdx.x & 31;
    float4 vi = reinterpret_cast<const float4*>(zis)[row * (D_K / 4) + lane];
    float4 vj = reinterpret_cast<const float4*>(zjs)[row * (D_K / 4) + lane];
    float a2 = vi.x * vi.x + vi.y * vi.y + vi.z * vi.z + vi.w * vi.w;
    float b2 = vj.x * vj.x + vj.y * vj.y + vj.z * vj.z + vj.w * vj.w;
    float d  = vi.x * vj.x + vi.y * vj.y + vi.z * vj.z + vi.w * vj.w;
#pragma unroll
    for (int o = 16; o; o >>= 1) {
        a2 += __shfl_xor_sync(0xffffffffu, a2, o);
        b2 += __shfl_xor_sync(0xffffffffu, b2, o);
        d  += __shfl_xor_sync(0xffffffffu, d, o);
    }
    float si = rsqrtf(fmaxf(a2, 1e-24f)) * (2.0f * LOG2E);
    float sj = rsqrtf(fmaxf(b2, 1e-24f));
    uint16_t lo, hi;
    asm("cvt.rn.satfinite.e4m3x2.f32 %0, %1, %2;" : "=h"(lo) : "f"(vi.y * si), "f"(vi.x * si));
    asm("cvt.rn.satfinite.e4m3x2.f32 %0, %1, %2;" : "=h"(hi) : "f"(vi.w * si), "f"(vi.z * si));
    g_a8[row * 32 + lane] = (uint32_t)lo | ((uint32_t)hi << 16);
    asm("cvt.rn.satfinite.e4m3x2.f32 %0, %1, %2;" : "=h"(lo) : "f"(vj.y * sj), "f"(vj.x * sj));
    asm("cvt.rn.satfinite.e4m3x2.f32 %0, %1, %2;" : "=h"(hi) : "f"(vj.w * sj), "f"(vj.z * sj));
    g_b8[row * 32 + lane] = (uint32_t)lo | ((uint32_t)hi << 16);
    if (lane == 0)
        g_diag[row] = d / fmaxf(sqrtf(a2) * sqrtf(b2), 1e-8f);
}

// ---------------------------------------------------------------------------
// stage one 128-col x 128-byte fp8 B chunk. Row j = 8 x 16B; swizzle c^(j&7).
// ---------------------------------------------------------------------------
__device__ __forceinline__ void stage_chunk(uint32_t smbase, int colbase, int tid) {
#pragma unroll
    for (int i = 0; i < 2; i++) {
        int u = tid + i * 512;
        int j = u >> 3, c = u & 7;
        const void* src = (const char*)g_b8 + (colbase + j) * 128 + c * 16;
        uint32_t dst = smbase + (((j << 3) + (c ^ (j & 7))) << 4);
        asm volatile("cp.async.cg.shared.global [%0], [%1], 16;" :: "r"(dst), "l"(src));
    }
    asm volatile("cp.async.commit_group;");
}

// ---------------------------------------------------------------------------
// main: 148 persistent CTAs x 512 threads (16 warps, 4/SMSP).
// Unit u: rowtile rt = u>>6 (128 rows), chunk ch = u&63 (128 cols).
// Warp (wr, wc): wr=warp&7 -> 16 rows, wc=warp>>3 -> 64 of 128 chunk cols.
// ---------------------------------------------------------------------------
__global__ void __launch_bounds__(512, 1) main_kernel() {
    extern __shared__ __align__(1024) unsigned char sm[];
    const uint32_t smb = smem_u32(sm);

    const int tid = threadIdx.x;
    const int lane = tid & 31;
    const int warp = tid >> 5;
    const int wr = warp & 7;
    const int wc = warp >> 3;
    const int g = lane >> 2;
    const int t4 = lane & 3;
    const int nb = wc * 64;
    const int rloc0 = wr * 16 + g;        // local row (0..127), +8 for second

    const int lo = (int)(((long)blockIdx.x * NUNITS) / NCTAS);
    const int hi = (int)(((long)(blockIdx.x + 1) * NUNITS) / NCTAS);

    // prologue: stage up to 3 units ahead
#pragma unroll
    for (int t = 0; t < 3; t++)
        if (lo + t < hi) stage_chunk(smb + ((lo + t) & 3) * CHUNK_BYTES,
                                     ((lo + t) & 63) * 128, tid);

    uint32_t aF[4][4];
    int cur_rt = -1;

    for (int u = lo; u < hi; u++) {
        const int rt = u >> 6;
        const int ch = u & 63;
        const int rem = hi - u - 1;
        if (rem >= 2)      asm volatile("cp.async.wait_group 2;");
        else if (rem == 1) asm volatile("cp.async.wait_group 1;");
        else               asm volatile("cp.async.wait_group 0;");
        __syncthreads();   // chunk u staged; all warps past prior epilogue

        if (u + 3 < hi)
            stage_chunk(smb + ((u + 3) & 3) * CHUNK_BYTES, ((u + 3) & 63) * 128, tid);

        if (rt != cur_rt) {   // reload A fragments for new rowtile (L2-hot)
            cur_rt = rt;
            const int r0 = rt * 128 + rloc0, r1 = r0 + 8;
#pragma unroll
            for (int ks = 0; ks < 4; ks++) {
                aF[ks][0] = g_a8[r0 * 32 + ks * 8 + t4];
                aF[ks][1] = g_a8[r1 * 32 + ks * 8 + t4];
                aF[ks][2] = g_a8[r0 * 32 + ks * 8 + 4 + t4];
                aF[ks][3] = g_a8[r1 * 32 + ks * 8 + 4 + t4];
            }
        }

        const uint32_t base = smb + (u & 3) * CHUNK_BYTES;
        float acc[8][4];
#pragma unroll
        for (int f = 0; f < 8; f++)
#pragma unroll
            for (int e = 0; e < 4; e++) acc[f][e] = 0.f;

#pragma unroll
        for (int ks = 0; ks < 4; ks++) {
            uint32_t bF[8][2];
#pragma unroll
            for (int nf = 0; nf < 4; nf++) {
                int j = nb + nf * 16 + ((lane >> 4) << 3) + (lane & 7);
                int c = 2 * ks + ((lane >> 3) & 1);
                uint32_t addr = base + (((j << 3) + (c ^ (j & 7))) << 4);
                uint32_t r0, r1, r2, r3;
                asm volatile("ldmatrix.sync.aligned.m8n8.x4.shared.b16 {%0,%1,%2,%3}, [%4];"
                             : "=r"(r0), "=r"(r1), "=r"(r2), "=r"(r3) : "r"(addr));
                bF[nf * 2][0] = r0;     bF[nf * 2][1] = r1;
                bF[nf * 2 + 1][0] = r2; bF[nf * 2 + 1][1] = r3;
            }
#pragma unroll
            for (int f = 0; f < 8; f++) {
                asm volatile(
                    "mma.sync.aligned.m16n8k32.row.col.f32.e4m3.e4m3.f32 "
                    "{%0,%1,%2,%3},{%4,%5,%6,%7},{%8,%9},{%0,%1,%2,%3};"
                    : "+f"(acc[f][0]), "+f"(acc[f][1]), "+f"(acc[f][2]), "+f"(acc[f][3])
                    : "r"(aF[ks][0]), "r"(aF[ks][1]), "r"(aF[ks][2]), "r"(aF[ks][3]),
                      "r"(bF[f][0]), "r"(bF[f][1]));
            }
        }

        float rs0 = 0.f, rs1 = 0.f;
        if (ch != rt) {
            // vector epilogue: f16x2 ex2, half2 partial sums (chunk-local, <=64)
            __half2 h0 = __float2half2_rn(0.f), h1 = h0;
#pragma unroll
            for (int f = 0; f < 8; f++) {
                uint32_t p, q;
                asm("cvt.rn.f16x2.f32 %0, %1, %2;" : "=r"(p) : "f"(acc[f][1]), "f"(acc[f][0]));
                asm("ex2.approx.f16x2 %0, %0;" : "+r"(p));
                h0 = __hadd2(h0, *reinterpret_cast<__half2*>(&p));
                asm("cvt.rn.f16x2.f32 %0, %1, %2;" : "=r"(q) : "f"(acc[f][3]), "f"(acc[f][2]));
                asm("ex2.approx.f16x2 %0, %0;" : "+r"(q));
                h1 = __hadd2(h1, *reinterpret_cast<__half2*>(&q));
            }
            float2 f0 = __half22float2(h0), f1 = __half22float2(h1);
            rs0 = f0.x + f0.y;
            rs1 = f1.x + f1.y;
        } else {
            // masked epilogue: rowtile == chunk (both 128-aligned) -> local test
#pragma unroll
            for (int f = 0; f < 8; f++) {
                int c0 = nb + f * 8 + 2 * t4;
#pragma unroll
                for (int e = 0; e < 4; e++) {
                    int rl = (e < 2) ? rloc0 : (rloc0 + 8);
                    int cl = c0 + (e & 1);
                    float ev = ex2f(acc[f][e]);
                    if ((rl >> 4) == (cl >> 4)) ev = 0.f;  // own block, diag incl.
                    if (e < 2) rs0 += ev; else rs1 += ev;
                }
            }
        }
        // quad reduction: lanes 4g..4g+3 hold cols of the same rows
        rs0 += __shfl_xor_sync(0xffffffffu, rs0, 1);
        rs0 += __shfl_xor_sync(0xffffffffu, rs0, 2);
        rs1 += __shfl_xor_sync(0xffffffffu, rs1, 1);
        rs1 += __shfl_xor_sync(0xffffffffu, rs1, 2);
        if (t4 == 0) {
            float* dst = &g_unit[(u * 2 + wc) * 128];
            dst[rloc0] = rs0;
            dst[rloc0 + 8] = rs1;
        }
    }
}

// ---------------------------------------------------------------------------
// finalize1: 64 CTAs x 128 threads; row r = blk*128+tid sums its 128 partials,
// computes loss, block-reduces into g_partial[blk].
// ---------------------------------------------------------------------------
__global__ void __launch_bounds__(128) finalize1_kernel() {
    __shared__ float red[128];
    const int rt = blockIdx.x;
    const int lr = threadIdx.x;
    float S = 0.f;
    const float* base = &g_unit[rt * 64 * 256];
#pragma unroll 8
    for (int c = 0; c < 64; c++)
        S += base[c * 256 + lr] + base[c * 256 + 128 + lr];
    float d = g_diag[rt * 128 + lr];
    float pos = 2.0f * d;             // sim / T
    S += ex2f(pos * LOG2E);           // add positive term
    red[lr] = logf(S) - pos;
    __syncthreads();
    for (int o = 64; o; o >>= 1) {
        if (lr < o) red[lr] += red[lr + o];
        __syncthreads();
    }
    if (lr == 0) g_partial[rt] = red[0];
}

__global__ void __launch_bounds__(64) finalize2_kernel(float* __restrict__ out) {
    __shared__ float red[64];
    int tid = threadIdx.x;
    red[tid] = g_partial[tid];
    __syncthreads();
    for (int o = 32; o; o >>= 1) {
        if (tid < o) red[tid] += red[tid + o];
        __syncthreads();
    }
    if (tid == 0) out[0] = red[0] * (1.0f / (float)B_N);
}

extern "C" void kernel_launch(void* const* d_in, const int* in_sizes, int n_in,
                              void* d_out, int out_size) {
    (void)in_sizes; (void)n_in; (void)out_size;
    const float* zis = (const float*)d_in[0];
    const float* zjs = (const float*)d_in[1];
    cudaFuncSetAttribute(main_kernel, cudaFuncAttributeMaxDynamicSharedMemorySize,
                         SMEM_TOTAL);
    prep_kernel<<<B_N * 32 / 256, 256>>>(zis, zjs);   // 1024 blocks
    main_kernel<<<NCTAS, 512, SMEM_TOTAL>>>();
    finalize1_kernel<<<64, 128>>>();
    finalize2_kernel<<<1, 64>>>((float*)d_out);
}

// round 10
// speedup vs baseline: 1.4919x; 1.4919x over previous
#include <cuda_runtime.h>
#include <cuda_fp16.h>
#include <cstdint>

// NTXentLoss fused, INT8 mma.sync (IMMA), persistent edition.
// B=8192, D=128, G=16, T=0.5
//   prep:     normalize rows, quantize to s8 (q = round(x_hat * 254), |q|<=~112);
//             exact fp32 diag cosine.
//   main:     148 CTAs x 512 threads; 4096 units (64 rowtiles x 64 chunks of
//             128x128). Per unit: mma.sync.m16n8k32.s8 (exact s32 dots),
//             epilogue: s32 -> f32 * C -> ex2.approx.f16x2 + block mask,
//             quad-reduced row partials -> g_unit (deterministic).
//   final1/2: per-row sum of 128 partials + loss; reduce 64 -> scalar.
// logit_log2 = dot_s32 * C, C = (2*log2e)/254^2; exp = exp2(logit_log2).

#define B_N 8192
#define D_K 128
#define NUNITS 4096                  // 64 rowtiles x 64 chunks
#define NCTAS 148
#define LOG2E 1.4426950408889634f
#define QS 254.0f                    // s8 quant scale on normalized components
#define CSCALE ((2.0f * LOG2E) / (QS * QS))
#define CHUNK_BYTES (128 * 128)      // 16 KB s8 B chunk
#define SMEM_TOTAL (4 * CHUNK_BYTES) // 64 KB ring

__device__ uint32_t g_a8[B_N * 32];   // zis s8x4, normalized * QS
__device__ uint32_t g_b8[B_N * 32];   // zjs s8x4, normalized * QS
__device__ float g_diag[B_N];         // exact fp32 cosine(zis_i, zjs_i)
__device__ float g_unit[NUNITS * 256];// per-unit, per-half row partials (4 MB)
__device__ float g_partial[64];

__device__ __forceinline__ uint32_t smem_u32(const void* p) {
    return (uint32_t)__cvta_generic_to_shared(p);
}
__device__ __forceinline__ float ex2f(float x) {
    float r;
    asm("ex2.approx.ftz.f32 %0, %1;" : "=f"(r) : "f"(x));
    return r;
}
__device__ __forceinline__ int q8(float x) {
    int q = __float2int_rn(x);
    return max(-127, min(127, q));
}

// ---------------------------------------------------------------------------
// prep: one warp per row; s8 quantization + exact diag, one pass.
// ---------------------------------------------------------------------------
__global__ void __launch_bounds__(256) prep_kernel(const float* __restrict__ zis,
                                                   const float* __restrict__ zjs) {
    int row = (blockIdx.x * 256 + threadIdx.x) >> 5;
    int lane = threadIdx.x & 31;
    float4 vi = reinterpret_cast<const float4*>(zis)[row * (D_K / 4) + lane];
    float4 vj = reinterpret_cast<const float4*>(zjs)[row * (D_K / 4) + lane];
    float a2 = vi.x * vi.x + vi.y * vi.y + vi.z * vi.z + vi.w * vi.w;
    float b2 = vj.x * vj.x + vj.y * vj.y + vj.z * vj.z + vj.w * vj.w;
    float d  = vi.x * vj.x + vi.y * vj.y + vi.z * vj.z + vi.w * vj.w;
#pragma unroll
    for (int o = 16; o; o >>= 1) {
        a2 += __shfl_xor_sync(0xffffffffu, a2, o);
        b2 += __shfl_xor_sync(0xffffffffu, b2, o);
        d  += __shfl_xor_sync(0xffffffffu, d, o);
    }
    float si = rsqrtf(fmaxf(a2, 1e-24f)) * QS;
    float sj = rsqrtf(fmaxf(b2, 1e-24f)) * QS;
    int q0 = q8(vi.x * si), q1 = q8(vi.y * si), q2 = q8(vi.z * si), q3 = q8(vi.w * si);
    g_a8[row * 32 + lane] = (uint32_t)(q0 & 0xFF) | ((uint32_t)(q1 & 0xFF) << 8)
                          | ((uint32_t)(q2 & 0xFF) << 16) | ((uint32_t)q3 << 24);
    q0 = q8(vj.x * sj); q1 = q8(vj.y * sj); q2 = q8(vj.z * sj); q3 = q8(vj.w * sj);
    g_b8[row * 32 + lane] = (uint32_t)(q0 & 0xFF) | ((uint32_t)(q1 & 0xFF) << 8)
                          | ((uint32_t)(q2 & 0xFF) << 16) | ((uint32_t)q3 << 24);
    if (lane == 0)
        g_diag[row] = d / fmaxf(sqrtf(a2) * sqrtf(b2), 1e-8f);
}

// ---------------------------------------------------------------------------
// stage one 128-col x 128-byte s8 B chunk. Row j = 8 x 16B; swizzle c^(j&7).
// ---------------------------------------------------------------------------
__device__ __forceinline__ void stage_chunk(uint32_t smbase, int colbase, int tid) {
#pragma unroll
    for (int i = 0; i < 2; i++) {
        int u = tid + i * 512;
        int j = u >> 3, c = u & 7;
        const void* src = (const char*)g_b8 + (colbase + j) * 128 + c * 16;
        uint32_t dst = smbase + (((j << 3) + (c ^ (j & 7))) << 4);
        asm volatile("cp.async.cg.shared.global [%0], [%1], 16;" :: "r"(dst), "l"(src));
    }
    asm volatile("cp.async.commit_group;");
}

// ---------------------------------------------------------------------------
// main: 148 persistent CTAs x 512 threads (16 warps, 4/SMSP).
// Unit u: rowtile rt = u>>6 (128 rows), chunk ch = u&63 (128 cols).
// Warp (wr, wc): wr=warp&7 -> 16 rows, wc=warp>>3 -> 64 of 128 chunk cols.
// ---------------------------------------------------------------------------
__global__ void __launch_bounds__(512, 1) main_kernel() {
    extern __shared__ __align__(1024) unsigned char sm[];
    const uint32_t smb = smem_u32(sm);

    const int tid = threadIdx.x;
    const int lane = tid & 31;
    const int warp = tid >> 5;
    const int wr = warp & 7;
    const int wc = warp >> 3;
    const int g = lane >> 2;
    const int t4 = lane & 3;
    const int nb = wc * 64;
    const int rloc0 = wr * 16 + g;        // local row (0..127), +8 for second

    const int lo = (int)(((long)blockIdx.x * NUNITS) / NCTAS);
    const int hi = (int)(((long)(blockIdx.x + 1) * NUNITS) / NCTAS);

#pragma unroll
    for (int t = 0; t < 3; t++)
        if (lo + t < hi) stage_chunk(smb + ((lo + t) & 3) * CHUNK_BYTES,
                                     ((lo + t) & 63) * 128, tid);

    uint32_t aF[4][4];
    int cur_rt = -1;

    for (int u = lo; u < hi; u++) {
        const int rt = u >> 6;
        const int ch = u & 63;
        const int rem = hi - u - 1;
        if (rem >= 2)      asm volatile("cp.async.wait_group 2;");
        else if (rem == 1) asm volatile("cp.async.wait_group 1;");
        else               asm volatile("cp.async.wait_group 0;");
        __syncthreads();   // chunk u staged; all warps past prior epilogue

        if (u + 3 < hi)
            stage_chunk(smb + ((u + 3) & 3) * CHUNK_BYTES, ((u + 3) & 63) * 128, tid);

        if (rt != cur_rt) {   // reload A fragments for new rowtile (L2-hot)
            cur_rt = rt;
            const int r0 = rt * 128 + rloc0, r1 = r0 + 8;
#pragma unroll
            for (int ks = 0; ks < 4; ks++) {
                aF[ks][0] = g_a8[r0 * 32 + ks * 8 + t4];
                aF[ks][1] = g_a8[r1 * 32 + ks * 8 + t4];
                aF[ks][2] = g_a8[r0 * 32 + ks * 8 + 4 + t4];
                aF[ks][3] = g_a8[r1 * 32 + ks * 8 + 4 + t4];
            }
        }

        const uint32_t base = smb + (u & 3) * CHUNK_BYTES;
        int acc[8][4];
#pragma unroll
        for (int f = 0; f < 8; f++)
#pragma unroll
            for (int e = 0; e < 4; e++) acc[f][e] = 0;

#pragma unroll
        for (int ks = 0; ks < 4; ks++) {
            uint32_t bF[8][2];
#pragma unroll
            for (int nf = 0; nf < 4; nf++) {
                int j = nb + nf * 16 + ((lane >> 4) << 3) + (lane & 7);
                int c = 2 * ks + ((lane >> 3) & 1);
                uint32_t addr = base + (((j << 3) + (c ^ (j & 7))) << 4);
                uint32_t r0, r1, r2, r3;
                asm volatile("ldmatrix.sync.aligned.m8n8.x4.shared.b16 {%0,%1,%2,%3}, [%4];"
                             : "=r"(r0), "=r"(r1), "=r"(r2), "=r"(r3) : "r"(addr));
                bF[nf * 2][0] = r0;     bF[nf * 2][1] = r1;
                bF[nf * 2 + 1][0] = r2; bF[nf * 2 + 1][1] = r3;
            }
#pragma unroll
            for (int f = 0; f < 8; f++) {
                asm volatile(
                    "mma.sync.aligned.m16n8k32.row.col.s32.s8.s8.s32 "
                    "{%0,%1,%2,%3},{%4,%5,%6,%7},{%8,%9},{%0,%1,%2,%3};"
                    : "+r"(acc[f][0]), "+r"(acc[f][1]), "+r"(acc[f][2]), "+r"(acc[f][3])
                    : "r"(aF[ks][0]), "r"(aF[ks][1]), "r"(aF[ks][2]), "r"(aF[ks][3]),
                      "r"(bF[f][0]), "r"(bF[f][1]));
            }
        }

        float rs0 = 0.f, rs1 = 0.f;
        if (ch != rt) {
            // vector epilogue: s32 -> f32*C -> f16x2 ex2, half2 partial sums
            __half2 h0 = __float2half2_rn(0.f), h1 = h0;
#pragma unroll
            for (int f = 0; f < 8; f++) {
                float a0 = (float)acc[f][0] * CSCALE, a1 = (float)acc[f][1] * CSCALE;
                float a2v = (float)acc[f][2] * CSCALE, a3 = (float)acc[f][3] * CSCALE;
                uint32_t p, q;
                asm("cvt.rn.f16x2.f32 %0, %1, %2;" : "=r"(p) : "f"(a1), "f"(a0));
                asm("ex2.approx.f16x2 %0, %0;" : "+r"(p));
                h0 = __hadd2(h0, *reinterpret_cast<__half2*>(&p));
                asm("cvt.rn.f16x2.f32 %0, %1, %2;" : "=r"(q) : "f"(a3), "f"(a2v));
                asm("ex2.approx.f16x2 %0, %0;" : "+r"(q));
                h1 = __hadd2(h1, *reinterpret_cast<__half2*>(&q));
            }
            float2 f0 = __half22float2(h0), f1 = __half22float2(h1);
            rs0 = f0.x + f0.y;
            rs1 = f1.x + f1.y;
        } else {
            // masked epilogue: rowtile == chunk (both 128-aligned) -> local test
#pragma unroll
            for (int f = 0; f < 8; f++) {
                int c0 = nb + f * 8 + 2 * t4;
#pragma unroll
                for (int e = 0; e < 4; e++) {
                    int rl = (e < 2) ? rloc0 : (rloc0 + 8);
                    int cl = c0 + (e & 1);
                    float ev = ex2f((float)acc[f][e] * CSCALE);
                    if ((rl >> 4) == (cl >> 4)) ev = 0.f;  // own block, diag incl.
                    if (e < 2) rs0 += ev; else rs1 += ev;
                }
            }
        }
        // quad reduction: lanes 4g..4g+3 hold cols of the same rows
        rs0 += __shfl_xor_sync(0xffffffffu, rs0, 1);
        rs0 += __shfl_xor_sync(0xffffffffu, rs0, 2);
        rs1 += __shfl_xor_sync(0xffffffffu, rs1, 1);
        rs1 += __shfl_xor_sync(0xffffffffu, rs1, 2);
        if (t4 == 0) {
            float* dst = &g_unit[(u * 2 + wc) * 128];
            dst[rloc0] = rs0;
            dst[rloc0 + 8] = rs1;
        }
    }
}

// ---------------------------------------------------------------------------
// finalize1: 64 CTAs x 128 threads; row r = blk*128+tid sums its 128 partials,
// computes loss, block-reduces into g_partial[blk].
// ---------------------------------------------------------------------------
__global__ void __launch_bounds__(128) finalize1_kernel() {
    __shared__ float red[128];
    const int rt = blockIdx.x;
    const int lr = threadIdx.x;
    float S = 0.f;
    const float* base = &g_unit[rt * 64 * 256];
#pragma unroll 8
    for (int c = 0; c < 64; c++)
        S += base[c * 256 + lr] + base[c * 256 + 128 + lr];
    float d = g_diag[rt * 128 + lr];
    float pos = 2.0f * d;             // sim / T
    S += ex2f(pos * LOG2E);           // add positive term
    red[lr] = logf(S) - pos;
    __syncthreads();
    for (int o = 64; o; o >>= 1) {
        if (lr < o) red[lr] += red[lr + o];
        __syncthreads();
    }
    if (lr == 0) g_partial[rt] = red[0];
}

__global__ void __launch_bounds__(64) finalize2_kernel(float* __restrict__ out) {
    __shared__ float red[64];
    int tid = threadIdx.x;
    red[tid] = g_partial[tid];
    __syncthreads();
    for (int o = 32; o; o >>= 1) {
        if (tid < o) red[tid] += red[tid + o];
        __syncthreads();
    }
    if (tid == 0) out[0] = red[0] * (1.0f / (float)B_N);
}

extern "C" void kernel_launch(void* const* d_in, const int* in_sizes, int n_in,
                              void* d_out, int out_size) {
    (void)in_sizes; (void)n_in; (void)out_size;
    const float* zis = (const float*)d_in[0];
    const float* zjs = (const float*)d_in[1];
    cudaFuncSetAttribute(main_kernel, cudaFuncAttributeMaxDynamicSharedMemorySize,
                         SMEM_TOTAL);
    prep_kernel<<<B_N * 32 / 256, 256>>>(zis, zjs);   // 1024 blocks
    main_kernel<<<NCTAS, 512, SMEM_TOTAL>>>();
    finalize1_kernel<<<64, 128>>>();
    finalize2_kernel<<<1, 64>>>((float*)d_out);
}

// round 12
// speedup vs baseline: 1.6521x; 1.1074x over previous
#include <cuda_runtime.h>
#include <cuda_fp16.h>
#include <cstdint>

// NTXentLoss fused, INT8 mma.sync (IMMA), persistent, de-phase-locked edition.
// B=8192, D=128, G=16, T=0.5
//   prep:     normalize rows, quantize to s8 (q = round(x_hat * 254));
//             exact fp32 diag cosine.
//   main:     148 CTAs x 512 threads; 4096 units (64 rowtiles x 64 chunks of
//             128x128). 6-deep smem ring, __syncthreads every 2 units so warps
//             drift within a 2-unit window (MUFU epilogue overlaps IMMA).
//   final:    per-row sum of 128 partials + loss; last-block reduces to scalar.
// logit_log2 = dot_s32 * C, C = (2*log2e)/254^2; exp = exp2(logit_log2).

#define B_N 8192
#define D_K 128
#define NUNITS 4096                  // 64 rowtiles x 64 chunks
#define NCTAS 148
#define LOG2E 1.4426950408889634f
#define QS 254.0f                    // s8 quant scale on normalized components
#define CSCALE ((2.0f * LOG2E) / (QS * QS))
#define CHUNK_BYTES (128 * 128)      // 16 KB s8 B chunk
#define RING 6
#define SMEM_TOTAL (RING * CHUNK_BYTES)   // 96 KB ring

__device__ uint32_t g_a8[B_N * 32];   // zis s8x4, normalized * QS
__device__ uint32_t g_b8[B_N * 32];   // zjs s8x4, normalized * QS
__device__ float g_diag[B_N];         // exact fp32 cosine(zis_i, zjs_i)
__device__ float g_unit[NUNITS * 256];// per-unit, per-half row partials (4 MB)
__device__ float g_partial[64];
__device__ int g_done;                // last-block ticket (resets each run)

__device__ __forceinline__ uint32_t smem_u32(const void* p) {
    return (uint32_t)__cvta_generic_to_shared(p);
}
__device__ __forceinline__ float ex2f(float x) {
    float r;
    asm("ex2.approx.ftz.f32 %0, %1;" : "=f"(r) : "f"(x));
    return r;
}
__device__ __forceinline__ int q8(float x) {
    int q = __float2int_rn(x);
    return max(-127, min(127, q));
}

// ---------------------------------------------------------------------------
// prep: one warp per row; s8 quantization + exact diag, one pass.
// ---------------------------------------------------------------------------
__global__ void __launch_bounds__(256) prep_kernel(const float* __restrict__ zis,
                                                   const float* __restrict__ zjs) {
    int row = (blockIdx.x * 256 + threadIdx.x) >> 5;
    int lane = threadIdx.x & 31;
    float4 vi = reinterpret_cast<const float4*>(zis)[row * (D_K / 4) + lane];
    float4 vj = reinterpret_cast<const float4*>(zjs)[row * (D_K / 4) + lane];
    float a2 = vi.x * vi.x + vi.y * vi.y + vi.z * vi.z + vi.w * vi.w;
    float b2 = vj.x * vj.x + vj.y * vj.y + vj.z * vj.z + vj.w * vj.w;
    float d  = vi.x * vj.x + vi.y * vj.y + vi.z * vj.z + vi.w * vj.w;
#pragma unroll
    for (int o = 16; o; o >>= 1) {
        a2 += __shfl_xor_sync(0xffffffffu, a2, o);
        b2 += __shfl_xor_sync(0xffffffffu, b2, o);
        d  += __shfl_xor_sync(0xffffffffu, d, o);
    }
    float si = rsqrtf(fmaxf(a2, 1e-24f)) * QS;
    float sj = rsqrtf(fmaxf(b2, 1e-24f)) * QS;
    int q0 = q8(vi.x * si), q1 = q8(vi.y * si), q2 = q8(vi.z * si), q3 = q8(vi.w * si);
    g_a8[row * 32 + lane] = (uint32_t)(q0 & 0xFF) | ((uint32_t)(q1 & 0xFF) << 8)
                          | ((uint32_t)(q2 & 0xFF) << 16) | ((uint32_t)q3 << 24);
    q0 = q8(vj.x * sj); q1 = q8(vj.y * sj); q2 = q8(vj.z * sj); q3 = q8(vj.w * sj);
    g_b8[row * 32 + lane] = (uint32_t)(q0 & 0xFF) | ((uint32_t)(q1 & 0xFF) << 8)
                          | ((uint32_t)(q2 & 0xFF) << 16) | ((uint32_t)q3 << 24);
    if (lane == 0)
        g_diag[row] = d / fmaxf(sqrtf(a2) * sqrtf(b2), 1e-8f);
}

// ---------------------------------------------------------------------------
// stage one 128-col x 128-byte s8 B chunk. Row j = 8 x 16B; swizzle c^(j&7).
// ---------------------------------------------------------------------------
__device__ __forceinline__ void stage_chunk(uint32_t smbase, int colbase, int tid) {
#pragma unroll
    for (int i = 0; i < 2; i++) {
        int u = tid + i * 512;
        int j = u >> 3, c = u & 7;
        const void* src = (const char*)g_b8 + (colbase + j) * 128 + c * 16;
        uint32_t dst = smbase + (((j << 3) + (c ^ (j & 7))) << 4);
        asm volatile("cp.async.cg.shared.global [%0], [%1], 16;" :: "r"(dst), "l"(src));
    }
    asm volatile("cp.async.commit_group;");
}

// ---------------------------------------------------------------------------
// main: 148 persistent CTAs x 512 threads (16 warps, 4/SMSP).
// Unit u: rowtile rt = u>>6 (128 rows), chunk ch = u&63 (128 cols).
// Warp (wr, wc): wr=warp&7 -> 16 rows, wc=warp>>3 -> 64 of 128 chunk cols.
// Sync every 2 units; 6-buffer ring lets warps drift 2 units apart so one
// warp's MUFU epilogue overlaps another's IMMA stream on the same SMSP.
// ---------------------------------------------------------------------------
__global__ void __launch_bounds__(512, 1) main_kernel() {
    extern __shared__ __align__(1024) unsigned char sm[];
    const uint32_t smb = smem_u32(sm);

    const int tid = threadIdx.x;
    const int lane = tid & 31;
    const int warp = tid >> 5;
    const int wr = warp & 7;
    const int wc = warp >> 3;
    const int g = lane >> 2;
    const int t4 = lane & 3;
    const int nb = wc * 64;
    const int rloc0 = wr * 16 + g;        // local row (0..127), +8 for second

    const int lo = (int)(((long)blockIdx.x * NUNITS) / NCTAS);
    const int hi = (int)(((long)(blockIdx.x + 1) * NUNITS) / NCTAS);

    // prologue: stage up to 4 chunks ahead
#pragma unroll
    for (int t = 0; t < 4; t++)
        if (lo + t < hi) stage_chunk(smb + ((lo + t) % RING) * CHUNK_BYTES,
                                     ((lo + t) & 63) * 128, tid);

    uint32_t aF[4][4];
    int cur_rt = -1;

    for (int u = lo; u < hi; u += 2) {
        const int umax = (u + 1 < hi) ? (u + 1) : u;
        // chunks staged so far reach min(hi-1, u+3); need umax complete
        const int pend = ((hi - 1 < u + 3) ? (hi - 1) : (u + 3)) - umax;
        if (pend <= 0)      asm volatile("cp.async.wait_group 0;");
        else if (pend == 1) asm volatile("cp.async.wait_group 1;");
        else                asm volatile("cp.async.wait_group 2;");
        __syncthreads();   // chunks u..umax visible; all warps past u-1

        if (u + 4 < hi)
            stage_chunk(smb + ((u + 4) % RING) * CHUNK_BYTES, ((u + 4) & 63) * 128, tid);
        if (u + 5 < hi)
            stage_chunk(smb + ((u + 5) % RING) * CHUNK_BYTES, ((u + 5) & 63) * 128, tid);

        for (int v = u; v <= umax; v++) {
            const int rt = v >> 6;
            const int ch = v & 63;

            if (rt != cur_rt) {   // reload A fragments for new rowtile (L2-hot)
                cur_rt = rt;
                const int r0 = rt * 128 + rloc0, r1 = r0 + 8;
#pragma unroll
                for (int ks = 0; ks < 4; ks++) {
                    aF[ks][0] = g_a8[r0 * 32 + ks * 8 + t4];
                    aF[ks][1] = g_a8[r1 * 32 + ks * 8 + t4];
                    aF[ks][2] = g_a8[r0 * 32 + ks * 8 + 4 + t4];
                    aF[ks][3] = g_a8[r1 * 32 + ks * 8 + 4 + t4];
                }
            }

            const uint32_t base = smb + (v % RING) * CHUNK_BYTES;
            int acc[8][4];
#pragma unroll
            for (int f = 0; f < 8; f++)
#pragma unroll
                for (int e = 0; e < 4; e++) acc[f][e] = 0;

#pragma unroll
            for (int ks = 0; ks < 4; ks++) {
                uint32_t bF[8][2];
#pragma unroll
                for (int nf = 0; nf < 4; nf++) {
                    int j = nb + nf * 16 + ((lane >> 4) << 3) + (lane & 7);
                    int c = 2 * ks + ((lane >> 3) & 1);
                    uint32_t addr = base + (((j << 3) + (c ^ (j & 7))) << 4);
                    uint32_t r0, r1, r2, r3;
                    asm volatile("ldmatrix.sync.aligned.m8n8.x4.shared.b16 {%0,%1,%2,%3}, [%4];"
                                 : "=r"(r0), "=r"(r1), "=r"(r2), "=r"(r3) : "r"(addr));
                    bF[nf * 2][0] = r0;     bF[nf * 2][1] = r1;
                    bF[nf * 2 + 1][0] = r2; bF[nf * 2 + 1][1] = r3;
                }
#pragma unroll
                for (int f = 0; f < 8; f++) {
                    asm volatile(
                        "mma.sync.aligned.m16n8k32.row.col.s32.s8.s8.s32 "
                        "{%0,%1,%2,%3},{%4,%5,%6,%7},{%8,%9},{%0,%1,%2,%3};"
                        : "+r"(acc[f][0]), "+r"(acc[f][1]), "+r"(acc[f][2]), "+r"(acc[f][3])
                        : "r"(aF[ks][0]), "r"(aF[ks][1]), "r"(aF[ks][2]), "r"(aF[ks][3]),
                          "r"(bF[f][0]), "r"(bF[f][1]));
                }
            }

            float rs0 = 0.f, rs1 = 0.f;
            if (ch != rt) {
                // vector epilogue: s32 -> f32*C -> f16x2 ex2, half2 partial sums
                __half2 h0 = __float2half2_rn(0.f), h1 = h0;
#pragma unroll
                for (int f = 0; f < 8; f++) {
                    float a0 = (float)acc[f][0] * CSCALE, a1 = (float)acc[f][1] * CSCALE;
                    float a2v = (float)acc[f][2] * CSCALE, a3 = (float)acc[f][3] * CSCALE;
                    uint32_t p, q;
                    asm("cvt.rn.f16x2.f32 %0, %1, %2;" : "=r"(p) : "f"(a1), "f"(a0));
                    asm("ex2.approx.f16x2 %0, %0;" : "+r"(p));
                    h0 = __hadd2(h0, *reinterpret_cast<__half2*>(&p));
                    asm("cvt.rn.f16x2.f32 %0, %1, %2;" : "=r"(q) : "f"(a3), "f"(a2v));
                    asm("ex2.approx.f16x2 %0, %0;" : "+r"(q));
                    h1 = __hadd2(h1, *reinterpret_cast<__half2*>(&q));
                }
                float2 f0 = __half22float2(h0), f1 = __half22float2(h1);
                rs0 = f0.x + f0.y;
                rs1 = f1.x + f1.y;
            } else {
                // masked epilogue: rowtile == chunk -> local block test
#pragma unroll
                for (int f = 0; f < 8; f++) {
                    int c0 = nb + f * 8 + 2 * t4;
#pragma unroll
                    for (int e = 0; e < 4; e++) {
                        int rl = (e < 2) ? rloc0 : (rloc0 + 8);
                        int cl = c0 + (e & 1);
                        float ev = ex2f((float)acc[f][e] * CSCALE);
                        if ((rl >> 4) == (cl >> 4)) ev = 0.f;  // own block, diag incl.
                        if (e < 2) rs0 += ev; else rs1 += ev;
                    }
                }
            }
            // quad reduction: lanes 4g..4g+3 hold cols of the same rows
            rs0 += __shfl_xor_sync(0xffffffffu, rs0, 1);
            rs0 += __shfl_xor_sync(0xffffffffu, rs0, 2);
            rs1 += __shfl_xor_sync(0xffffffffu, rs1, 1);
            rs1 += __shfl_xor_sync(0xffffffffu, rs1, 2);
            if (t4 == 0) {
                float* dst = &g_unit[(v * 2 + wc) * 128];
                dst[rloc0] = rs0;
                dst[rloc0 + 8] = rs1;
            }
        }
    }
}

// ---------------------------------------------------------------------------
// finalize: 64 CTAs x 128 threads; row r = blk*128+tid sums its 128 partials,
// computes loss, block-reduces; last block sums all 64 in fixed order.
// ---------------------------------------------------------------------------
__global__ void __launch_bounds__(128) finalize_kernel(float* __restrict__ out) {
    __shared__ float red[128];
    const int rt = blockIdx.x;
    const int lr = threadIdx.x;
    float S = 0.f;
    const float* base = &g_unit[rt * 64 * 256];
#pragma unroll 8
    for (int c = 0; c < 64; c++)
        S += base[c * 256 + lr] + base[c * 256 + 128 + lr];
    float d = g_diag[rt * 128 + lr];
    float pos = 2.0f * d;             // sim / T
    S += ex2f(pos * LOG2E);           // add positive term
    red[lr] = logf(S) - pos;
    __syncthreads();
    for (int o = 64; o; o >>= 1) {
        if (lr < o) red[lr] += red[lr + o];
        __syncthreads();
    }
    if (lr == 0) {
        g_partial[rt] = red[0];
        __threadfence();
        if (atomicAdd(&g_done, 1) == 63) {   // last block: deterministic sum
            float s = 0.f;
#pragma unroll
            for (int i = 0; i < 64; i++) s += g_partial[i];
            out[0] = s * (1.0f / (float)B_N);
            g_done = 0;                      // reset for next graph replay
        }
    }
}

extern "C" void kernel_launch(void* const* d_in, const int* in_sizes, int n_in,
                              void* d_out, int out_size) {
    (void)in_sizes; (void)n_in; (void)out_size;
    const float* zis = (const float*)d_in[0];
    const float* zjs = (const float*)d_in[1];
    cudaFuncSetAttribute(main_kernel, cudaFuncAttributeMaxDynamicSharedMemorySize,
                         SMEM_TOTAL);
    prep_kernel<<<B_N * 32 / 256, 256>>>(zis, zjs);   // 1024 blocks
    main_kernel<<<NCTAS, 512, SMEM_TOTAL>>>();
    finalize_kernel<<<64, 128>>>((float*)d_out);
}